// round 10
// baseline (speedup 1.0000x reference)
#include <cuda_runtime.h>
#include <cuda_bf16.h>
#include <cstdint>
#include <cstddef>

#define NG 50000
#define ND 20000
#define HD 128
#define EGG 800000
#define EGDA 400000
#define ELAB 200000
#define ETOT (EGG + 2 * EGDA)
#define NTOT (NG + ND + NG)
#define MM 16384
#define WU 32768
#define WUB 16384
#define NGP 50048   // 391 * 128
#define NDP 20096   // 157 * 128
#define GBR 391
#define DBR 157

// ---------------- scratch ----------------
__device__ __nv_bfloat16 d_xg_h[(size_t)NGP * HD];
__device__ __nv_bfloat16 d_xg_l[(size_t)NGP * HD];
__device__ __nv_bfloat16 d_xd_h[(size_t)NDP * HD];
__device__ __nv_bfloat16 d_xd_l[(size_t)NDP * HD];
__device__ __nv_bfloat16 d_agg_gg_h[(size_t)NGP * HD];
__device__ __nv_bfloat16 d_agg_gg_l[(size_t)NGP * HD];
__device__ __nv_bfloat16 d_agg_rev_h[(size_t)NGP * HD];
__device__ __nv_bfloat16 d_agg_rev_l[(size_t)NGP * HD];
__device__ __nv_bfloat16 d_agg_d_h[(size_t)NDP * HD];
__device__ __nv_bfloat16 d_agg_d_l[(size_t)NDP * HD];
__device__ float d_g1[(size_t)NG * HD];
__device__ float d_d1[(size_t)ND * HD];
__device__ float d_g2[(size_t)NG * HD];
__device__ float d_d2[(size_t)ND * HD];
__device__ float d_rdeg_gg[NG];
__device__ float d_rdeg_rev[NG];
__device__ float d_rdeg_d[ND];
__device__ int d_ideg[NTOT];
__device__ int d_ptr_gg[NG + 1];
__device__ int d_ptr_d[ND + 1];
__device__ int d_ptr_rev[NG + 1];
__device__ int d_cur_gg[NG];
__device__ int d_cur_d[ND];
__device__ int d_cur_rev[NG];
__device__ int d_idx_gg[EGG];
__device__ int d_idx_d[EGDA];
__device__ int d_idx_rev[EGDA];
__device__ __nv_bfloat16 d_Wh[10 * MM];
__device__ __nv_bfloat16 d_Wl[10 * MM];
__device__ float d_bg[2][HD];
__device__ float d_bd[2][HD];
__device__ float d_bn_acc[512];

__device__ __forceinline__ void split2(float x, float y, uint32_t& h, uint32_t& l) {
    __nv_bfloat162 hb = __floats2bfloat162_rn(x, y);
    float2 f = __bfloat1622float2(hb);
    __nv_bfloat162 lb = __floats2bfloat162_rn(x - f.x, y - f.y);
    h = *(uint32_t*)&hb;
    l = *(uint32_t*)&lb;
}

// ---------------- CSR build ----------------
__global__ void init_kernel() {
    int i = blockIdx.x * blockDim.x + threadIdx.x;
    if (i < NTOT) d_ideg[i] = 0;
    else if (i < NTOT + 512) d_bn_acc[i - NTOT] = 0.f;
}

__global__ void deg_all_kernel(const int* __restrict__ gg_dst, const int* __restrict__ gda_dst,
                               const int* __restrict__ gda_src) {
    int i = blockIdx.x * blockDim.x + threadIdx.x;
    if (i < EGG) {
        atomicAdd(&d_ideg[__ldg(&gg_dst[i])], 1);
    } else if (i < EGG + EGDA) {
        atomicAdd(&d_ideg[NG + __ldg(&gda_dst[i - EGG])], 1);
    } else if (i < ETOT) {
        atomicAdd(&d_ideg[NG + ND + __ldg(&gda_src[i - EGG - EGDA])], 1);
    }
}

__global__ void scan_all_kernel() {
    __shared__ int sm[1024];
    int rel = blockIdx.x;
    const int* deg;
    int n;
    int* ptr;
    int* cur;
    float* rdeg;
    if (rel == 0) { deg = d_ideg; n = NG; ptr = d_ptr_gg; cur = d_cur_gg; rdeg = d_rdeg_gg; }
    else if (rel == 1) { deg = d_ideg + NG; n = ND; ptr = d_ptr_d; cur = d_cur_d; rdeg = d_rdeg_d; }
    else { deg = d_ideg + NG + ND; n = NG; ptr = d_ptr_rev; cur = d_cur_rev; rdeg = d_rdeg_rev; }
    int tid = threadIdx.x;
    int chunk = (n + 1023) >> 10;
    int lo = tid * chunk;
    int hi = min(lo + chunk, n);
    int s = 0;
    for (int i = lo; i < hi; ++i) s += deg[i];
    sm[tid] = s;
    __syncthreads();
    for (int off = 1; off < 1024; off <<= 1) {
        int v = 0;
        if (tid >= off) v = sm[tid - off];
        __syncthreads();
        sm[tid] += v;
        __syncthreads();
    }
    int run = sm[tid] - s;
    for (int i = lo; i < hi; ++i) {
        int dg = deg[i];
        ptr[i] = run;
        cur[i] = run;
        rdeg[i] = 1.0f / fmaxf((float)dg, 1.0f);
        run += dg;
    }
    if (tid == 1023) ptr[n] = sm[1023];
}

__global__ void fill_all_kernel(const int* __restrict__ gg_src, const int* __restrict__ gg_dst,
                                const int* __restrict__ gda_src, const int* __restrict__ gda_dst) {
    int i = blockIdx.x * blockDim.x + threadIdx.x;
    if (i < EGG) {
        int p = atomicAdd(&d_cur_gg[__ldg(&gg_dst[i])], 1);
        d_idx_gg[p] = __ldg(&gg_src[i]);
    } else if (i < EGG + EGDA) {
        int e = i - EGG;
        int p = atomicAdd(&d_cur_d[__ldg(&gda_dst[e])], 1);
        d_idx_d[p] = __ldg(&gda_src[e]);
    } else if (i < ETOT) {
        int e = i - EGG - EGDA;
        int p = atomicAdd(&d_cur_rev[__ldg(&gda_src[e])], 1);
        d_idx_rev[p] = __ldg(&gda_dst[e]);
    }
}

// ---------------- fp32 -> hi/lo shadow (layer-1 inputs) ----------------
__global__ void tobf16_kernel(const float* __restrict__ xg, const float* __restrict__ xd) {
    int i = blockIdx.x * blockDim.x + threadIdx.x;
    const float* x;
    __nv_bfloat16 *oh, *ol;
    if (i < NG * 32) { x = xg; oh = d_xg_h; ol = d_xg_l; }
    else if (i < (NG + ND) * 32) { x = xd; oh = d_xd_h; ol = d_xd_l; i -= NG * 32; }
    else return;
    float4 v = *(const float4*)&x[(size_t)i * 4];
    uint2 uh, ul;
    split2(v.x, v.y, uh.x, ul.x);
    split2(v.z, v.w, uh.y, ul.y);
    *(uint2*)&oh[(size_t)i * 4] = uh;
    *(uint2*)&ol[(size_t)i * 4] = ul;
}

// ---------------- fused gather (8-wide MLP) ----------------
__global__ __launch_bounds__(256) void gather_all_kernel() {
    int w = (blockIdx.x * blockDim.x + threadIdx.x) >> 5;
    int lane = threadIdx.x & 31;
    const __nv_bfloat16 *Xh, *Xl;
    const int* ptr;
    const int* idx;
    const float* rdeg;
    __nv_bfloat16 *Oh, *Ol;
    int r;
    if (w < NG) {
        Xh = d_xg_h; Xl = d_xg_l; ptr = d_ptr_gg; idx = d_idx_gg; rdeg = d_rdeg_gg;
        Oh = d_agg_gg_h; Ol = d_agg_gg_l; r = w;
    } else if (w < NG + ND) {
        Xh = d_xg_h; Xl = d_xg_l; ptr = d_ptr_d; idx = d_idx_d; rdeg = d_rdeg_d;
        Oh = d_agg_d_h; Ol = d_agg_d_l; r = w - NG;
    } else if (w < NTOT) {
        Xh = d_xd_h; Xl = d_xd_l; ptr = d_ptr_rev; idx = d_idx_rev; rdeg = d_rdeg_rev;
        Oh = d_agg_rev_h; Ol = d_agg_rev_l; r = w - NG - ND;
    } else return;
    int s = __ldg(&ptr[r]);
    int e = __ldg(&ptr[r + 1]);
    float4 a0 = make_float4(0.f, 0.f, 0.f, 0.f);
    float4 a1 = a0, a2 = a0, a3 = a0;
    int j = s;
    for (; j + 7 < e; j += 8) {
        size_t b[8];
#pragma unroll
        for (int q = 0; q < 8; ++q) b[q] = (size_t)__ldg(&idx[j + q]) * HD + lane * 4;
        uint2 h[8], l[8];
#pragma unroll
        for (int q = 0; q < 8; ++q) { h[q] = *(const uint2*)&Xh[b[q]]; l[q] = *(const uint2*)&Xl[b[q]]; }
#pragma unroll
        for (int q = 0; q < 8; ++q) {
            float2 p0 = __bfloat1622float2(*(__nv_bfloat162*)&h[q].x);
            float2 q0 = __bfloat1622float2(*(__nv_bfloat162*)&l[q].x);
            float2 p1 = __bfloat1622float2(*(__nv_bfloat162*)&h[q].y);
            float2 q1 = __bfloat1622float2(*(__nv_bfloat162*)&l[q].y);
            float4* a = (q & 3) == 0 ? &a0 : (q & 3) == 1 ? &a1 : (q & 3) == 2 ? &a2 : &a3;
            a->x += p0.x + q0.x; a->y += p0.y + q0.y;
            a->z += p1.x + q1.x; a->w += p1.y + q1.y;
        }
    }
    for (; j + 3 < e; j += 4) {
        size_t b[4];
#pragma unroll
        for (int q = 0; q < 4; ++q) b[q] = (size_t)__ldg(&idx[j + q]) * HD + lane * 4;
        uint2 h[4], l[4];
#pragma unroll
        for (int q = 0; q < 4; ++q) { h[q] = *(const uint2*)&Xh[b[q]]; l[q] = *(const uint2*)&Xl[b[q]]; }
#pragma unroll
        for (int q = 0; q < 4; ++q) {
            float2 p0 = __bfloat1622float2(*(__nv_bfloat162*)&h[q].x);
            float2 q0 = __bfloat1622float2(*(__nv_bfloat162*)&l[q].x);
            float2 p1 = __bfloat1622float2(*(__nv_bfloat162*)&h[q].y);
            float2 q1 = __bfloat1622float2(*(__nv_bfloat162*)&l[q].y);
            float4* a = q == 0 ? &a0 : q == 1 ? &a1 : q == 2 ? &a2 : &a3;
            a->x += p0.x + q0.x; a->y += p0.y + q0.y;
            a->z += p1.x + q1.x; a->w += p1.y + q1.y;
        }
    }
    for (; j < e; ++j) {
        size_t b0 = (size_t)__ldg(&idx[j]) * HD + lane * 4;
        uint2 h0 = *(const uint2*)&Xh[b0], l0 = *(const uint2*)&Xl[b0];
        float2 p, q;
        p = __bfloat1622float2(*(__nv_bfloat162*)&h0.x); q = __bfloat1622float2(*(__nv_bfloat162*)&l0.x);
        a0.x += p.x + q.x; a0.y += p.y + q.y;
        p = __bfloat1622float2(*(__nv_bfloat162*)&h0.y); q = __bfloat1622float2(*(__nv_bfloat162*)&l0.y);
        a0.z += p.x + q.x; a0.w += p.y + q.y;
    }
    float rr = __ldg(&rdeg[r]);
    float ox = (a0.x + a1.x + a2.x + a3.x) * rr;
    float oy = (a0.y + a1.y + a2.y + a3.y) * rr;
    float oz = (a0.z + a1.z + a2.z + a3.z) * rr;
    float ow = (a0.w + a1.w + a2.w + a3.w) * rr;
    uint2 uh, ul;
    split2(ox, oy, uh.x, ul.x);
    split2(oz, ow, uh.y, ul.y);
    size_t ob = (size_t)r * HD + lane * 4;
    *(uint2*)&Oh[ob] = uh;
    *(uint2*)&Ol[ob] = ul;
}

// ---------------- fused weight prep ----------------
__global__ __launch_bounds__(256) void wprep_kernel(
    const float* __restrict__ Wd1, const float* __restrict__ Ws1, const float* __restrict__ Wu1,
    const float* __restrict__ Wd2, const float* __restrict__ Ws2, const float* __restrict__ Wu2,
    __nv_bfloat16* __restrict__ Wh, __nv_bfloat16* __restrict__ Wl) {
    __shared__ __align__(16) float Xs[16][132];
    __shared__ __align__(16) float Ws_[16][128];
    int mtx = blockIdx.x;
    int l = mtx / 5, j = mtx % 5;
    const float* Wdl = l ? Wd2 : Wd1;
    const float* Wsl = l ? Ws2 : Ws1;
    const float* Wul = l ? Wu2 : Wu1;
    const float* X0 = nullptr;
    const float* W0 = nullptr;
    const float* X1 = nullptr;
    const float* W1 = nullptr;
    float scale = 1.f;
    switch (j) {
        case 0: X0 = Wdl; W0 = Wul; X1 = Wdl + 2 * MM; W1 = Wul + 2 * WU; scale = 0.5f; break;
        case 1: X0 = Wsl; W0 = Wul + WUB; scale = 0.5f; break;
        case 2: X0 = Wsl + 2 * MM; W0 = Wul + 2 * WU + WUB; scale = 0.5f; break;
        case 3: X0 = Wdl + MM; W0 = Wul + WU; scale = 1.f; break;
        case 4: X0 = Wsl + MM; W0 = Wul + WU + WUB; scale = 1.f; break;
    }
    int tid = threadIdx.x;
    float acc[8][8];
#pragma unroll
    for (int i = 0; i < 8; ++i)
#pragma unroll
        for (int q = 0; q < 8; ++q) acc[i][q] = 0.f;
    const float* Xp[2] = {X0, X1};
    const float* Wp[2] = {W0, W1};
    int rA = tid >> 2, kq = tid & 3, krow = tid >> 4, cq = tid & 15;
    int tx = tid & 15, ty = tid >> 4;
    for (int t = 0; t < 2; ++t) {
        const float* X = Xp[t];
        if (!X) continue;
        const float* W = Wp[t];
        for (int kc = 0; kc < 8; ++kc) {
#pragma unroll
            for (int h = 0; h < 2; ++h) {
                int r = rA + h * 64;
                float4 v = *(const float4*)&X[(size_t)r * 128 + kc * 16 + kq * 4];
                Xs[kq * 4 + 0][r] = v.x;
                Xs[kq * 4 + 1][r] = v.y;
                Xs[kq * 4 + 2][r] = v.z;
                Xs[kq * 4 + 3][r] = v.w;
            }
#pragma unroll
            for (int h = 0; h < 2; ++h) {
                int c = cq + h * 16;
                *(float4*)&Ws_[krow][c * 4] = *(const float4*)&W[(size_t)(kc * 16 + krow) * 128 + c * 4];
            }
            __syncthreads();
#pragma unroll
            for (int k = 0; k < 16; ++k) {
                float a[8], b[8];
                *(float4*)&a[0] = *(const float4*)&Xs[k][ty * 8];
                *(float4*)&a[4] = *(const float4*)&Xs[k][ty * 8 + 4];
                *(float4*)&b[0] = *(const float4*)&Ws_[k][tx * 8];
                *(float4*)&b[4] = *(const float4*)&Ws_[k][tx * 8 + 4];
#pragma unroll
                for (int i = 0; i < 8; ++i)
#pragma unroll
                    for (int q = 0; q < 8; ++q) acc[i][q] = fmaf(a[i], b[q], acc[i][q]);
            }
            __syncthreads();
        }
    }
    __nv_bfloat16* oh = Wh + (size_t)mtx * MM;
    __nv_bfloat16* ol = Wl + (size_t)mtx * MM;
#pragma unroll
    for (int i = 0; i < 8; ++i) {
        int krow2 = ty * 8 + i;
#pragma unroll
        for (int q = 0; q < 8; ++q) {
            int col = tx * 8 + q;
            float v = acc[i][q] * scale;
            __nv_bfloat16 h = __float2bfloat16(v);
            oh[col * 128 + krow2] = h;
            ol[col * 128 + krow2] = __float2bfloat16(v - __bfloat162float(h));
        }
    }
}

// ---------------- mma.sync node GEMM (128-row tile, occ 1, fused BN stats) ----------------
#define LDA 136
#define SM_MAT (128 * LDA)
#define SMEM_TOTAL (4 * SM_MAT * 2)

__device__ __forceinline__ void mma_bf16(float* c, const uint32_t* a, uint32_t b0, uint32_t b1) {
    asm volatile(
        "mma.sync.aligned.m16n8k16.row.col.f32.bf16.bf16.f32 "
        "{%0,%1,%2,%3}, {%4,%5,%6,%7}, {%8,%9}, {%0,%1,%2,%3};"
        : "+f"(c[0]), "+f"(c[1]), "+f"(c[2]), "+f"(c[3])
        : "r"(a[0]), "r"(a[1]), "r"(a[2]), "r"(a[3]), "r"(b0), "r"(b1));
}
__device__ __forceinline__ void ldm_x4(uint32_t* r, uint32_t saddr) {
    asm volatile("ldmatrix.sync.aligned.m8n8.x4.shared.b16 {%0,%1,%2,%3}, [%4];"
                 : "=r"(r[0]), "=r"(r[1]), "=r"(r[2]), "=r"(r[3]) : "r"(saddr));
}

__global__ __launch_bounds__(256, 1) void mmagemm_kernel(
    const __nv_bfloat16* __restrict__ WhL, const __nv_bfloat16* __restrict__ WlL,
    const float* __restrict__ biasg, const float* __restrict__ biasd,
    float* __restrict__ outg, float* __restrict__ outd, int do_bn) {
    extern __shared__ __nv_bfloat16 smem[];
    __nv_bfloat16* Ah = smem;
    __nv_bfloat16* Al = smem + SM_MAT;
    __nv_bfloat16* Bh = smem + 2 * SM_MAT;
    __nv_bfloat16* Bl = smem + 3 * SM_MAT;
    __shared__ float bnsum[128];
    __shared__ float bnsq[128];

    int tid = threadIdx.x;
    int wid = tid >> 5;
    int lane = tid & 31;

    bool gene = (int)blockIdx.x < GBR;
    int m0, n, nterms;
    const __nv_bfloat16* AHa[3];
    const __nv_bfloat16* ALa[3];
    const __nv_bfloat16* Bha[3];
    const __nv_bfloat16* Bla[3];
    const float* bias;
    float* out;
    if (gene) {
        m0 = blockIdx.x * 128; n = NG; nterms = 3;
        AHa[0] = d_xg_h; ALa[0] = d_xg_l;
        AHa[1] = d_agg_gg_h; ALa[1] = d_agg_gg_l;
        AHa[2] = d_agg_rev_h; ALa[2] = d_agg_rev_l;
        Bha[0] = WhL; Bha[1] = WhL + MM; Bha[2] = WhL + 2 * MM;
        Bla[0] = WlL; Bla[1] = WlL + MM; Bla[2] = WlL + 2 * MM;
        bias = biasg; out = outg;
    } else {
        m0 = (blockIdx.x - GBR) * 128; n = ND; nterms = 2;
        AHa[0] = d_xd_h; ALa[0] = d_xd_l;
        AHa[1] = d_agg_d_h; ALa[1] = d_agg_d_l;
        AHa[2] = d_xd_h; ALa[2] = d_xd_l;
        Bha[0] = WhL + 3 * MM; Bha[1] = WhL + 4 * MM; Bha[2] = WhL + 3 * MM;
        Bla[0] = WlL + 3 * MM; Bla[1] = WlL + 4 * MM; Bla[2] = WlL + 3 * MM;
        bias = biasd; out = outd;
    }

    if (do_bn && tid < 128) { bnsum[tid] = 0.f; bnsq[tid] = 0.f; }

    int wr = (wid & 3) * 32;
    int wc = (wid >> 2) * 64;
    int g = lane >> 2;
    int tg = lane & 3;

    uint32_t sAh = (uint32_t)__cvta_generic_to_shared(Ah);
    uint32_t sAl = (uint32_t)__cvta_generic_to_shared(Al);
    uint32_t sBh = (uint32_t)__cvta_generic_to_shared(Bh);
    uint32_t sBl = (uint32_t)__cvta_generic_to_shared(Bl);
    uint32_t aoff[2];
#pragma unroll
    for (int mt = 0; mt < 2; ++mt) {
        int row = wr + mt * 16 + ((lane >> 3) & 1) * 8 + (lane & 7);
        int kc = (lane >> 4) * 8;
        aoff[mt] = (uint32_t)((row * LDA + kc) * 2);
    }
    uint32_t boff[4];
#pragma unroll
    for (int m = 0; m < 4; ++m) {
        int nn = wc + m * 16 + ((lane >> 4) & 1) * 8 + (lane & 7);
        int kc = ((lane >> 3) & 1) * 8;
        boff[m] = (uint32_t)((nn * LDA + kc) * 2);
    }

    float acc[2][8][4];
#pragma unroll
    for (int mt = 0; mt < 2; ++mt)
#pragma unroll
        for (int nt = 0; nt < 8; ++nt)
#pragma unroll
            for (int q = 0; q < 4; ++q) acc[mt][nt][q] = 0.f;

    for (int t = 0; t < nterms; ++t) {
        __syncthreads();
        {
            const __nv_bfloat16* ah = AHa[t];
            const __nv_bfloat16* al = ALa[t];
            const __nv_bfloat16* bh = Bha[t];
            const __nv_bfloat16* bl = Bla[t];
#pragma unroll
            for (int c = 0; c < 8; ++c) {
                int chunk = c * 256 + tid;
                int row = chunk >> 4;
                int k0 = (chunk & 15) * 8;
                int d = row * LDA + k0;
                size_t so = (size_t)(m0 + row) * 128 + k0;
                *(uint4*)&Ah[d] = *(const uint4*)(ah + so);
                *(uint4*)&Al[d] = *(const uint4*)(al + so);
                *(uint4*)&Bh[d] = *(const uint4*)(bh + (size_t)chunk * 8);
                *(uint4*)&Bl[d] = *(const uint4*)(bl + (size_t)chunk * 8);
            }
        }
        __syncthreads();
#pragma unroll
        for (int ks = 0; ks < 8; ++ks) {
            uint32_t kb2 = (uint32_t)(ks * 32);
            uint32_t ah[2][4], al[2][4], bh[4][4], bl[4][4];
            ldm_x4(ah[0], sAh + aoff[0] + kb2);
            ldm_x4(ah[1], sAh + aoff[1] + kb2);
            ldm_x4(al[0], sAl + aoff[0] + kb2);
            ldm_x4(al[1], sAl + aoff[1] + kb2);
#pragma unroll
            for (int m = 0; m < 4; ++m) {
                ldm_x4(bh[m], sBh + boff[m] + kb2);
                ldm_x4(bl[m], sBl + boff[m] + kb2);
            }
#pragma unroll
            for (int mt = 0; mt < 2; ++mt)
#pragma unroll
                for (int m = 0; m < 4; ++m) {
                    mma_bf16(acc[mt][2 * m], ah[mt], bh[m][0], bh[m][1]);
                    mma_bf16(acc[mt][2 * m], ah[mt], bl[m][0], bl[m][1]);
                    mma_bf16(acc[mt][2 * m], al[mt], bh[m][0], bh[m][1]);
                    mma_bf16(acc[mt][2 * m + 1], ah[mt], bh[m][2], bh[m][3]);
                    mma_bf16(acc[mt][2 * m + 1], ah[mt], bl[m][2], bl[m][3]);
                    mma_bf16(acc[mt][2 * m + 1], al[mt], bh[m][2], bh[m][3]);
                }
        }
    }

    // epilogue: bias, store, optional BN partials
#pragma unroll
    for (int mt = 0; mt < 2; ++mt) {
        int r0v = m0 + wr + mt * 16 + g;
        int r1v = r0v + 8;
#pragma unroll
        for (int nt = 0; nt < 8; ++nt) {
            int col = wc + nt * 8 + tg * 2;
            float b0 = __ldg(&bias[col]);
            float b1 = __ldg(&bias[col + 1]);
            float v00 = acc[mt][nt][0] + b0, v01 = acc[mt][nt][1] + b1;
            float v10 = acc[mt][nt][2] + b0, v11 = acc[mt][nt][3] + b1;
            if (r0v < n) *(float2*)&out[(size_t)r0v * 128 + col] = make_float2(v00, v01);
            if (r1v < n) *(float2*)&out[(size_t)r1v * 128 + col] = make_float2(v10, v11);
            if (do_bn) {
                float s0 = 0.f, q0 = 0.f, s1 = 0.f, q1 = 0.f;
                if (r0v < n) { s0 += v00; q0 += v00 * v00; s1 += v01; q1 += v01 * v01; }
                if (r1v < n) { s0 += v10; q0 += v10 * v10; s1 += v11; q1 += v11 * v11; }
                atomicAdd(&bnsum[col], s0);
                atomicAdd(&bnsq[col], q0);
                atomicAdd(&bnsum[col + 1], s1);
                atomicAdd(&bnsq[col + 1], q1);
            }
        }
    }
    if (do_bn) {
        __syncthreads();
        if (tid < 128) {
            int off = gene ? 0 : 128;
            atomicAdd(&d_bn_acc[off + tid], bnsum[tid]);
            atomicAdd(&d_bn_acc[256 + off + tid], bnsq[tid]);
        }
    }
}

// ---------------- bias combine ----------------
__global__ void bias_combine_kernel(const float* __restrict__ bd1, const float* __restrict__ bs1,
                                    const float* __restrict__ bu1, const float* __restrict__ Wu1,
                                    const float* __restrict__ bd2, const float* __restrict__ bs2,
                                    const float* __restrict__ bu2, const float* __restrict__ Wu2) {
    int layer = blockIdx.x >> 1;
    int which = blockIdx.x & 1;
    int h = threadIdx.x;
    const float* bd = layer ? bd2 : bd1;
    const float* bs = layer ? bs2 : bs1;
    const float* bu = layer ? bu2 : bu1;
    const float* Wu = layer ? Wu2 : Wu1;
    auto cfun = [&](int i) {
        float s = bu[i * 128 + h];
        const float* wt = Wu + (size_t)i * WU;
        for (int k = 0; k < 128; ++k) s = fmaf(bd[i * 128 + k], wt[k * 128 + h], s);
        const float* wb = wt + WUB;
        for (int k = 0; k < 128; ++k) s = fmaf(bs[i * 128 + k], wb[k * 128 + h], s);
        return s;
    };
    if (which == 0)
        d_bg[layer][h] = 0.5f * (cfun(0) + cfun(2));
    else
        d_bd[layer][h] = cfun(1);
}

// ---------------- BN apply (final folded in); emits hi/lo planes ----------------
__global__ void bn_apply_kernel(const float* __restrict__ xg, const float* __restrict__ xd,
                                const float* __restrict__ gamma, const float* __restrict__ beta) {
    int i = blockIdx.x * blockDim.x + threadIdx.x;
    int which;
    const float* x;
    __nv_bfloat16 *oh, *ol;
    if (i < NG * 32) { which = 0; x = xg; oh = d_xg_h; ol = d_xg_l; }
    else if (i < (NG + ND) * 32) { which = 1; x = xd; oh = d_xd_h; ol = d_xd_l; i -= NG * 32; }
    else return;
    int q = i & 31;
    int c = q * 4;
    int off = which * 128;
    float nn = which == 0 ? (float)NG : (float)ND;
    float sc[4], sh[4];
#pragma unroll
    for (int k = 0; k < 4; ++k) {
        float mean = __ldg(&d_bn_acc[off + c + k]) / nn;
        float var = __ldg(&d_bn_acc[256 + off + c + k]) / nn - mean * mean;
        float s = __ldg(&gamma[off + c + k]) * rsqrtf(var + 1e-5f);
        sc[k] = s;
        sh[k] = __ldg(&beta[off + c + k]) - mean * s;
    }
    float4 v = *(const float4*)&x[(size_t)i * 4];
    v.x = fmaf(v.x, sc[0], sh[0]);
    v.y = fmaf(v.y, sc[1], sh[1]);
    v.z = fmaf(v.z, sc[2], sh[2]);
    v.w = fmaf(v.w, sc[3], sh[3]);
    v.x = v.x >= 0.f ? v.x : 0.01f * v.x;
    v.y = v.y >= 0.f ? v.y : 0.01f * v.y;
    v.z = v.z >= 0.f ? v.z : 0.01f * v.z;
    v.w = v.w >= 0.f ? v.w : 0.01f * v.w;
    uint2 uh, ul;
    split2(v.x, v.y, uh.x, ul.x);
    split2(v.z, v.w, uh.y, ul.y);
    *(uint2*)&oh[(size_t)i * 4] = uh;
    *(uint2*)&ol[(size_t)i * 4] = ul;
}

// ---------------- decoder ----------------
__global__ void decode_kernel(const int* __restrict__ ls, const int* __restrict__ ld,
                              float* __restrict__ out) {
    int gw = (blockIdx.x * blockDim.x + threadIdx.x) >> 5;
    int lane = threadIdx.x & 31;
    if (gw >= ELAB) return;
    int a = __ldg(&ls[gw]);
    int b = __ldg(&ld[gw]);
    float4 u = *(const float4*)&d_g2[(size_t)a * 128 + lane * 4];
    float4 v = *(const float4*)&d_d2[(size_t)b * 128 + lane * 4];
    float s = u.x * v.x + u.y * v.y + u.z * v.z + u.w * v.w;
#pragma unroll
    for (int o = 16; o; o >>= 1) s += __shfl_xor_sync(0xFFFFFFFFu, s, o);
    if (lane == 0) out[gw] = s;
}

// ---------------- launch ----------------
static inline int cdiv(int a, int b) { return (a + b - 1) / b; }

extern "C" void kernel_launch(void* const* d_in, const int* in_sizes, int n_in,
                              void* d_out, int out_size) {
    const float* x_gene = (const float*)d_in[0];
    const float* x_dis  = (const float*)d_in[1];
    const float* W_dst1 = (const float*)d_in[2];
    const float* W_src1 = (const float*)d_in[3];
    const float* W_upd1 = (const float*)d_in[4];
    const float* b_dst1 = (const float*)d_in[5];
    const float* b_src1 = (const float*)d_in[6];
    const float* b_upd1 = (const float*)d_in[7];
    const float* W_dst2 = (const float*)d_in[8];
    const float* W_src2 = (const float*)d_in[9];
    const float* W_upd2 = (const float*)d_in[10];
    const float* b_dst2 = (const float*)d_in[11];
    const float* b_src2 = (const float*)d_in[12];
    const float* b_upd2 = (const float*)d_in[13];
    const float* bn_gamma = (const float*)d_in[14];
    const float* bn_beta  = (const float*)d_in[15];
    const int* gg_src  = (const int*)d_in[16];
    const int* gg_dst  = (const int*)d_in[17];
    const int* gda_src = (const int*)d_in[18];
    const int* gda_dst = (const int*)d_in[19];
    const int* label_src = (const int*)d_in[20];
    const int* label_dst = (const int*)d_in[21];
    float* out = (float*)d_out;

    static cudaStream_t s2 = nullptr;
    static cudaEvent_t e0 = nullptr, e1 = nullptr;
    if (!s2) {
        cudaFuncSetAttribute(mmagemm_kernel, cudaFuncAttributeMaxDynamicSharedMemorySize, SMEM_TOTAL);
        cudaStreamCreateWithFlags(&s2, cudaStreamNonBlocking);
        cudaEventCreateWithFlags(&e0, cudaEventDisableTiming);
        cudaEventCreateWithFlags(&e1, cudaEventDisableTiming);
    }

    float *g1, *d1, *g2, *d2, *bg, *bd;
    __nv_bfloat16 *Wh, *Wl;
    cudaGetSymbolAddress((void**)&g1, d_g1);
    cudaGetSymbolAddress((void**)&d1, d_d1);
    cudaGetSymbolAddress((void**)&g2, d_g2);
    cudaGetSymbolAddress((void**)&d2, d_d2);
    cudaGetSymbolAddress((void**)&Wh, d_Wh);
    cudaGetSymbolAddress((void**)&Wl, d_Wl);
    cudaGetSymbolAddress((void**)&bg, d_bg);
    cudaGetSymbolAddress((void**)&bd, d_bd);

    // fork: side stream converts inputs + preps weights while main builds CSR
    cudaEventRecord(e0, 0);
    cudaStreamWaitEvent(s2, e0, 0);
    tobf16_kernel<<<cdiv((NG + ND) * 32, 256), 256, 0, s2>>>(x_gene, x_dis);
    wprep_kernel<<<10, 256, 0, s2>>>(W_dst1, W_src1, W_upd1, W_dst2, W_src2, W_upd2, Wh, Wl);
    bias_combine_kernel<<<4, 128, 0, s2>>>(b_dst1, b_src1, b_upd1, W_upd1,
                                           b_dst2, b_src2, b_upd2, W_upd2);
    cudaEventRecord(e1, s2);

    // main: CSR build
    init_kernel<<<cdiv(NTOT + 512, 256), 256>>>();
    deg_all_kernel<<<cdiv(ETOT, 256), 256>>>(gg_dst, gda_dst, gda_src);
    scan_all_kernel<<<3, 1024>>>();
    fill_all_kernel<<<cdiv(ETOT, 256), 256>>>(gg_src, gg_dst, gda_src, gda_dst);

    // join
    cudaStreamWaitEvent(0, e1, 0);

    // layer-1 aggregation + GEMM (BN stats fused into epilogue)
    gather_all_kernel<<<cdiv(NTOT * 32, 256), 256>>>();
    mmagemm_kernel<<<GBR + DBR, 256, SMEM_TOTAL>>>(Wh, Wl, bg, bd, g1, d1, 1);

    // BN apply (final folded) -> hi/lo shadows
    bn_apply_kernel<<<cdiv((NG + ND) * 32, 256), 256>>>(g1, d1, bn_gamma, bn_beta);

    // layer-2 aggregation + GEMM
    gather_all_kernel<<<cdiv(NTOT * 32, 256), 256>>>();
    mmagemm_kernel<<<GBR + DBR, 256, SMEM_TOTAL>>>(Wh + 5 * MM, Wl + 5 * MM,
                                                   bg + HD, bd + HD, g2, d2, 0);

    // decoder
    decode_kernel<<<cdiv(ELAB * 32, 256), 256>>>(label_src, label_dst, out);
}

// round 11
// speedup vs baseline: 1.2000x; 1.2000x over previous
#include <cuda_runtime.h>
#include <cuda_bf16.h>
#include <cstdint>
#include <cstddef>

#define NG 50000
#define ND 20000
#define HD 128
#define EGG 800000
#define EGDA 400000
#define ELAB 200000
#define ETOT (EGG + 2 * EGDA)
#define NTOT (NG + ND + NG)
#define MM 16384
#define WU 32768
#define WUB 16384
#define NGP 50048   // 391 * 128
#define NDP 20096   // 157 * 128
#define GBR 391
#define DBR 157

// ---------------- scratch ----------------
__device__ __nv_bfloat16 d_xg_h[(size_t)NGP * HD];
__device__ __nv_bfloat16 d_xg_l[(size_t)NGP * HD];
__device__ __nv_bfloat16 d_xd_h[(size_t)NDP * HD];
__device__ __nv_bfloat16 d_xd_l[(size_t)NDP * HD];
__device__ __nv_bfloat16 d_agg_gg_h[(size_t)NGP * HD];
__device__ __nv_bfloat16 d_agg_gg_l[(size_t)NGP * HD];
__device__ __nv_bfloat16 d_agg_rev_h[(size_t)NGP * HD];
__device__ __nv_bfloat16 d_agg_rev_l[(size_t)NGP * HD];
__device__ __nv_bfloat16 d_agg_d_h[(size_t)NDP * HD];
__device__ __nv_bfloat16 d_agg_d_l[(size_t)NDP * HD];
__device__ float d_g1[(size_t)NG * HD];
__device__ float d_d1[(size_t)ND * HD];
__device__ float d_g2[(size_t)NG * HD];
__device__ float d_d2[(size_t)ND * HD];
__device__ float d_rdeg_gg[NG];
__device__ float d_rdeg_rev[NG];
__device__ float d_rdeg_d[ND];
__device__ int d_ideg[NTOT];
__device__ int d_ptr_gg[NG + 1];
__device__ int d_ptr_d[ND + 1];
__device__ int d_ptr_rev[NG + 1];
__device__ int d_cur_gg[NG];
__device__ int d_cur_d[ND];
__device__ int d_cur_rev[NG];
__device__ int d_idx_gg[EGG];
__device__ int d_idx_d[EGDA];
__device__ int d_idx_rev[EGDA];
__device__ __nv_bfloat16 d_Wh[10 * MM];
__device__ __nv_bfloat16 d_Wl[10 * MM];
__device__ float d_bg[2][HD];
__device__ float d_bd[2][HD];
__device__ float d_bn_acc[512];

__device__ __forceinline__ void split2(float x, float y, uint32_t& h, uint32_t& l) {
    __nv_bfloat162 hb = __floats2bfloat162_rn(x, y);
    float2 f = __bfloat1622float2(hb);
    __nv_bfloat162 lb = __floats2bfloat162_rn(x - f.x, y - f.y);
    h = *(uint32_t*)&hb;
    l = *(uint32_t*)&lb;
}

// ---------------- CSR build ----------------
__global__ void init_kernel() {
    int i = blockIdx.x * blockDim.x + threadIdx.x;
    if (i < NTOT) d_ideg[i] = 0;
    else if (i < NTOT + 512) d_bn_acc[i - NTOT] = 0.f;
}

__global__ void deg_all_kernel(const int* __restrict__ gg_dst, const int* __restrict__ gda_dst,
                               const int* __restrict__ gda_src) {
    int i = blockIdx.x * blockDim.x + threadIdx.x;
    if (i < EGG) {
        atomicAdd(&d_ideg[__ldg(&gg_dst[i])], 1);
    } else if (i < EGG + EGDA) {
        atomicAdd(&d_ideg[NG + __ldg(&gda_dst[i - EGG])], 1);
    } else if (i < ETOT) {
        atomicAdd(&d_ideg[NG + ND + __ldg(&gda_src[i - EGG - EGDA])], 1);
    }
}

__global__ void scan_all_kernel() {
    __shared__ int sm[1024];
    int rel = blockIdx.x;
    const int* deg;
    int n;
    int* ptr;
    int* cur;
    float* rdeg;
    if (rel == 0) { deg = d_ideg; n = NG; ptr = d_ptr_gg; cur = d_cur_gg; rdeg = d_rdeg_gg; }
    else if (rel == 1) { deg = d_ideg + NG; n = ND; ptr = d_ptr_d; cur = d_cur_d; rdeg = d_rdeg_d; }
    else { deg = d_ideg + NG + ND; n = NG; ptr = d_ptr_rev; cur = d_cur_rev; rdeg = d_rdeg_rev; }
    int tid = threadIdx.x;
    int chunk = (n + 1023) >> 10;
    int lo = tid * chunk;
    int hi = min(lo + chunk, n);
    int s = 0;
    for (int i = lo; i < hi; ++i) s += deg[i];
    sm[tid] = s;
    __syncthreads();
    for (int off = 1; off < 1024; off <<= 1) {
        int v = 0;
        if (tid >= off) v = sm[tid - off];
        __syncthreads();
        sm[tid] += v;
        __syncthreads();
    }
    int run = sm[tid] - s;
    for (int i = lo; i < hi; ++i) {
        int dg = deg[i];
        ptr[i] = run;
        cur[i] = run;
        rdeg[i] = 1.0f / fmaxf((float)dg, 1.0f);
        run += dg;
    }
    if (tid == 1023) ptr[n] = sm[1023];
}

__global__ void fill_all_kernel(const int* __restrict__ gg_src, const int* __restrict__ gg_dst,
                                const int* __restrict__ gda_src, const int* __restrict__ gda_dst) {
    int i = blockIdx.x * blockDim.x + threadIdx.x;
    if (i < EGG) {
        int p = atomicAdd(&d_cur_gg[__ldg(&gg_dst[i])], 1);
        d_idx_gg[p] = __ldg(&gg_src[i]);
    } else if (i < EGG + EGDA) {
        int e = i - EGG;
        int p = atomicAdd(&d_cur_d[__ldg(&gda_dst[e])], 1);
        d_idx_d[p] = __ldg(&gda_src[e]);
    } else if (i < ETOT) {
        int e = i - EGG - EGDA;
        int p = atomicAdd(&d_cur_rev[__ldg(&gda_src[e])], 1);
        d_idx_rev[p] = __ldg(&gda_dst[e]);
    }
}

// ---------------- fp32 -> hi/lo shadow (layer-1 inputs) ----------------
__global__ void tobf16_kernel(const float* __restrict__ xg, const float* __restrict__ xd) {
    int i = blockIdx.x * blockDim.x + threadIdx.x;
    const float* x;
    __nv_bfloat16 *oh, *ol;
    if (i < NG * 32) { x = xg; oh = d_xg_h; ol = d_xg_l; }
    else if (i < (NG + ND) * 32) { x = xd; oh = d_xd_h; ol = d_xd_l; i -= NG * 32; }
    else return;
    float4 v = *(const float4*)&x[(size_t)i * 4];
    uint2 uh, ul;
    split2(v.x, v.y, uh.x, ul.x);
    split2(v.z, v.w, uh.y, ul.y);
    *(uint2*)&oh[(size_t)i * 4] = uh;
    *(uint2*)&ol[(size_t)i * 4] = ul;
}

// ---------------- fused gather (8-wide MLP) ----------------
__global__ __launch_bounds__(256) void gather_all_kernel() {
    int w = (blockIdx.x * blockDim.x + threadIdx.x) >> 5;
    int lane = threadIdx.x & 31;
    const __nv_bfloat16 *Xh, *Xl;
    const int* ptr;
    const int* idx;
    const float* rdeg;
    __nv_bfloat16 *Oh, *Ol;
    int r;
    if (w < NG) {
        Xh = d_xg_h; Xl = d_xg_l; ptr = d_ptr_gg; idx = d_idx_gg; rdeg = d_rdeg_gg;
        Oh = d_agg_gg_h; Ol = d_agg_gg_l; r = w;
    } else if (w < NG + ND) {
        Xh = d_xg_h; Xl = d_xg_l; ptr = d_ptr_d; idx = d_idx_d; rdeg = d_rdeg_d;
        Oh = d_agg_d_h; Ol = d_agg_d_l; r = w - NG;
    } else if (w < NTOT) {
        Xh = d_xd_h; Xl = d_xd_l; ptr = d_ptr_rev; idx = d_idx_rev; rdeg = d_rdeg_rev;
        Oh = d_agg_rev_h; Ol = d_agg_rev_l; r = w - NG - ND;
    } else return;
    int s = __ldg(&ptr[r]);
    int e = __ldg(&ptr[r + 1]);
    float4 a0 = make_float4(0.f, 0.f, 0.f, 0.f);
    float4 a1 = a0, a2 = a0, a3 = a0;
    int j = s;
    for (; j + 7 < e; j += 8) {
        size_t b[8];
#pragma unroll
        for (int q = 0; q < 8; ++q) b[q] = (size_t)__ldg(&idx[j + q]) * HD + lane * 4;
        uint2 h[8], l[8];
#pragma unroll
        for (int q = 0; q < 8; ++q) { h[q] = *(const uint2*)&Xh[b[q]]; l[q] = *(const uint2*)&Xl[b[q]]; }
#pragma unroll
        for (int q = 0; q < 8; ++q) {
            float2 p0 = __bfloat1622float2(*(__nv_bfloat162*)&h[q].x);
            float2 q0 = __bfloat1622float2(*(__nv_bfloat162*)&l[q].x);
            float2 p1 = __bfloat1622float2(*(__nv_bfloat162*)&h[q].y);
            float2 q1 = __bfloat1622float2(*(__nv_bfloat162*)&l[q].y);
            float4* a = (q & 3) == 0 ? &a0 : (q & 3) == 1 ? &a1 : (q & 3) == 2 ? &a2 : &a3;
            a->x += p0.x + q0.x; a->y += p0.y + q0.y;
            a->z += p1.x + q1.x; a->w += p1.y + q1.y;
        }
    }
    for (; j + 3 < e; j += 4) {
        size_t b[4];
#pragma unroll
        for (int q = 0; q < 4; ++q) b[q] = (size_t)__ldg(&idx[j + q]) * HD + lane * 4;
        uint2 h[4], l[4];
#pragma unroll
        for (int q = 0; q < 4; ++q) { h[q] = *(const uint2*)&Xh[b[q]]; l[q] = *(const uint2*)&Xl[b[q]]; }
#pragma unroll
        for (int q = 0; q < 4; ++q) {
            float2 p0 = __bfloat1622float2(*(__nv_bfloat162*)&h[q].x);
            float2 q0 = __bfloat1622float2(*(__nv_bfloat162*)&l[q].x);
            float2 p1 = __bfloat1622float2(*(__nv_bfloat162*)&h[q].y);
            float2 q1 = __bfloat1622float2(*(__nv_bfloat162*)&l[q].y);
            float4* a = q == 0 ? &a0 : q == 1 ? &a1 : q == 2 ? &a2 : &a3;
            a->x += p0.x + q0.x; a->y += p0.y + q0.y;
            a->z += p1.x + q1.x; a->w += p1.y + q1.y;
        }
    }
    for (; j < e; ++j) {
        size_t b0 = (size_t)__ldg(&idx[j]) * HD + lane * 4;
        uint2 h0 = *(const uint2*)&Xh[b0], l0 = *(const uint2*)&Xl[b0];
        float2 p, q;
        p = __bfloat1622float2(*(__nv_bfloat162*)&h0.x); q = __bfloat1622float2(*(__nv_bfloat162*)&l0.x);
        a0.x += p.x + q.x; a0.y += p.y + q.y;
        p = __bfloat1622float2(*(__nv_bfloat162*)&h0.y); q = __bfloat1622float2(*(__nv_bfloat162*)&l0.y);
        a0.z += p.x + q.x; a0.w += p.y + q.y;
    }
    float rr = __ldg(&rdeg[r]);
    float ox = (a0.x + a1.x + a2.x + a3.x) * rr;
    float oy = (a0.y + a1.y + a2.y + a3.y) * rr;
    float oz = (a0.z + a1.z + a2.z + a3.z) * rr;
    float ow = (a0.w + a1.w + a2.w + a3.w) * rr;
    uint2 uh, ul;
    split2(ox, oy, uh.x, ul.x);
    split2(oz, ow, uh.y, ul.y);
    size_t ob = (size_t)r * HD + lane * 4;
    *(uint2*)&Oh[ob] = uh;
    *(uint2*)&Ol[ob] = ul;
}

// ---------------- fused weight prep ----------------
__global__ __launch_bounds__(256) void wprep_kernel(
    const float* __restrict__ Wd1, const float* __restrict__ Ws1, const float* __restrict__ Wu1,
    const float* __restrict__ Wd2, const float* __restrict__ Ws2, const float* __restrict__ Wu2,
    __nv_bfloat16* __restrict__ Wh, __nv_bfloat16* __restrict__ Wl) {
    __shared__ __align__(16) float Xs[16][132];
    __shared__ __align__(16) float Ws_[16][128];
    int mtx = blockIdx.x;
    int l = mtx / 5, j = mtx % 5;
    const float* Wdl = l ? Wd2 : Wd1;
    const float* Wsl = l ? Ws2 : Ws1;
    const float* Wul = l ? Wu2 : Wu1;
    const float* X0 = nullptr;
    const float* W0 = nullptr;
    const float* X1 = nullptr;
    const float* W1 = nullptr;
    float scale = 1.f;
    switch (j) {
        case 0: X0 = Wdl; W0 = Wul; X1 = Wdl + 2 * MM; W1 = Wul + 2 * WU; scale = 0.5f; break;
        case 1: X0 = Wsl; W0 = Wul + WUB; scale = 0.5f; break;
        case 2: X0 = Wsl + 2 * MM; W0 = Wul + 2 * WU + WUB; scale = 0.5f; break;
        case 3: X0 = Wdl + MM; W0 = Wul + WU; scale = 1.f; break;
        case 4: X0 = Wsl + MM; W0 = Wul + WU + WUB; scale = 1.f; break;
    }
    int tid = threadIdx.x;
    float acc[8][8];
#pragma unroll
    for (int i = 0; i < 8; ++i)
#pragma unroll
        for (int q = 0; q < 8; ++q) acc[i][q] = 0.f;
    const float* Xp[2] = {X0, X1};
    const float* Wp[2] = {W0, W1};
    int rA = tid >> 2, kq = tid & 3, krow = tid >> 4, cq = tid & 15;
    int tx = tid & 15, ty = tid >> 4;
    for (int t = 0; t < 2; ++t) {
        const float* X = Xp[t];
        if (!X) continue;
        const float* W = Wp[t];
        for (int kc = 0; kc < 8; ++kc) {
#pragma unroll
            for (int h = 0; h < 2; ++h) {
                int r = rA + h * 64;
                float4 v = *(const float4*)&X[(size_t)r * 128 + kc * 16 + kq * 4];
                Xs[kq * 4 + 0][r] = v.x;
                Xs[kq * 4 + 1][r] = v.y;
                Xs[kq * 4 + 2][r] = v.z;
                Xs[kq * 4 + 3][r] = v.w;
            }
#pragma unroll
            for (int h = 0; h < 2; ++h) {
                int c = cq + h * 16;
                *(float4*)&Ws_[krow][c * 4] = *(const float4*)&W[(size_t)(kc * 16 + krow) * 128 + c * 4];
            }
            __syncthreads();
#pragma unroll
            for (int k = 0; k < 16; ++k) {
                float a[8], b[8];
                *(float4*)&a[0] = *(const float4*)&Xs[k][ty * 8];
                *(float4*)&a[4] = *(const float4*)&Xs[k][ty * 8 + 4];
                *(float4*)&b[0] = *(const float4*)&Ws_[k][tx * 8];
                *(float4*)&b[4] = *(const float4*)&Ws_[k][tx * 8 + 4];
#pragma unroll
                for (int i = 0; i < 8; ++i)
#pragma unroll
                    for (int q = 0; q < 8; ++q) acc[i][q] = fmaf(a[i], b[q], acc[i][q]);
            }
            __syncthreads();
        }
    }
    __nv_bfloat16* oh = Wh + (size_t)mtx * MM;
    __nv_bfloat16* ol = Wl + (size_t)mtx * MM;
#pragma unroll
    for (int i = 0; i < 8; ++i) {
        int krow2 = ty * 8 + i;
#pragma unroll
        for (int q = 0; q < 8; ++q) {
            int col = tx * 8 + q;
            float v = acc[i][q] * scale;
            __nv_bfloat16 h = __float2bfloat16(v);
            oh[col * 128 + krow2] = h;
            ol[col * 128 + krow2] = __float2bfloat16(v - __bfloat162float(h));
        }
    }
}

// ---------------- mma.sync node GEMM (R8 structure: 128-row tile, occ 1) ----------------
#define LDA 136
#define SM_MAT (128 * LDA)
#define SMEM_TOTAL (4 * SM_MAT * 2)

__device__ __forceinline__ void mma_bf16(float* c, const uint32_t* a, uint32_t b0, uint32_t b1) {
    asm volatile(
        "mma.sync.aligned.m16n8k16.row.col.f32.bf16.bf16.f32 "
        "{%0,%1,%2,%3}, {%4,%5,%6,%7}, {%8,%9}, {%0,%1,%2,%3};"
        : "+f"(c[0]), "+f"(c[1]), "+f"(c[2]), "+f"(c[3])
        : "r"(a[0]), "r"(a[1]), "r"(a[2]), "r"(a[3]), "r"(b0), "r"(b1));
}
__device__ __forceinline__ void ldm_x4(uint32_t* r, uint32_t saddr) {
    asm volatile("ldmatrix.sync.aligned.m8n8.x4.shared.b16 {%0,%1,%2,%3}, [%4];"
                 : "=r"(r[0]), "=r"(r[1]), "=r"(r[2]), "=r"(r[3]) : "r"(saddr));
}

__global__ __launch_bounds__(256, 1) void mmagemm_kernel(
    const __nv_bfloat16* __restrict__ WhL, const __nv_bfloat16* __restrict__ WlL,
    const float* __restrict__ biasg, const float* __restrict__ biasd,
    float* __restrict__ outg, float* __restrict__ outd) {
    extern __shared__ __nv_bfloat16 smem[];
    __nv_bfloat16* Ah = smem;
    __nv_bfloat16* Al = smem + SM_MAT;
    __nv_bfloat16* Bh = smem + 2 * SM_MAT;
    __nv_bfloat16* Bl = smem + 3 * SM_MAT;

    int tid = threadIdx.x;
    int wid = tid >> 5;
    int lane = tid & 31;

    bool gene = (int)blockIdx.x < GBR;
    int m0, n, nterms;
    const __nv_bfloat16* AHa[3];
    const __nv_bfloat16* ALa[3];
    const __nv_bfloat16* Bha[3];
    const __nv_bfloat16* Bla[3];
    const float* bias;
    float* out;
    if (gene) {
        m0 = blockIdx.x * 128; n = NG; nterms = 3;
        AHa[0] = d_xg_h; ALa[0] = d_xg_l;
        AHa[1] = d_agg_gg_h; ALa[1] = d_agg_gg_l;
        AHa[2] = d_agg_rev_h; ALa[2] = d_agg_rev_l;
        Bha[0] = WhL; Bha[1] = WhL + MM; Bha[2] = WhL + 2 * MM;
        Bla[0] = WlL; Bla[1] = WlL + MM; Bla[2] = WlL + 2 * MM;
        bias = biasg; out = outg;
    } else {
        m0 = (blockIdx.x - GBR) * 128; n = ND; nterms = 2;
        AHa[0] = d_xd_h; ALa[0] = d_xd_l;
        AHa[1] = d_agg_d_h; ALa[1] = d_agg_d_l;
        AHa[2] = d_xd_h; ALa[2] = d_xd_l;
        Bha[0] = WhL + 3 * MM; Bha[1] = WhL + 4 * MM; Bha[2] = WhL + 3 * MM;
        Bla[0] = WlL + 3 * MM; Bla[1] = WlL + 4 * MM; Bla[2] = WlL + 3 * MM;
        bias = biasd; out = outd;
    }

    int wr = (wid & 3) * 32;
    int wc = (wid >> 2) * 64;
    int g = lane >> 2;
    int tg = lane & 3;

    uint32_t sAh = (uint32_t)__cvta_generic_to_shared(Ah);
    uint32_t sAl = (uint32_t)__cvta_generic_to_shared(Al);
    uint32_t sBh = (uint32_t)__cvta_generic_to_shared(Bh);
    uint32_t sBl = (uint32_t)__cvta_generic_to_shared(Bl);
    uint32_t aoff[2];
#pragma unroll
    for (int mt = 0; mt < 2; ++mt) {
        int row = wr + mt * 16 + ((lane >> 3) & 1) * 8 + (lane & 7);
        int kc = (lane >> 4) * 8;
        aoff[mt] = (uint32_t)((row * LDA + kc) * 2);
    }
    uint32_t boff[4];
#pragma unroll
    for (int m = 0; m < 4; ++m) {
        int nn = wc + m * 16 + ((lane >> 4) & 1) * 8 + (lane & 7);
        int kc = ((lane >> 3) & 1) * 8;
        boff[m] = (uint32_t)((nn * LDA + kc) * 2);
    }

    float acc[2][8][4];
#pragma unroll
    for (int mt = 0; mt < 2; ++mt)
#pragma unroll
        for (int nt = 0; nt < 8; ++nt)
#pragma unroll
            for (int q = 0; q < 4; ++q) acc[mt][nt][q] = 0.f;

    for (int t = 0; t < nterms; ++t) {
        __syncthreads();
        {
            const __nv_bfloat16* ah = AHa[t];
            const __nv_bfloat16* al = ALa[t];
            const __nv_bfloat16* bh = Bha[t];
            const __nv_bfloat16* bl = Bla[t];
#pragma unroll
            for (int c = 0; c < 8; ++c) {
                int chunk = c * 256 + tid;
                int row = chunk >> 4;
                int k0 = (chunk & 15) * 8;
                int d = row * LDA + k0;
                size_t so = (size_t)(m0 + row) * 128 + k0;
                *(uint4*)&Ah[d] = *(const uint4*)(ah + so);
                *(uint4*)&Al[d] = *(const uint4*)(al + so);
                *(uint4*)&Bh[d] = *(const uint4*)(bh + (size_t)chunk * 8);
                *(uint4*)&Bl[d] = *(const uint4*)(bl + (size_t)chunk * 8);
            }
        }
        __syncthreads();
#pragma unroll
        for (int ks = 0; ks < 8; ++ks) {
            uint32_t kb2 = (uint32_t)(ks * 32);
            uint32_t ah[2][4], al[2][4], bh[4][4], bl[4][4];
            ldm_x4(ah[0], sAh + aoff[0] + kb2);
            ldm_x4(ah[1], sAh + aoff[1] + kb2);
            ldm_x4(al[0], sAl + aoff[0] + kb2);
            ldm_x4(al[1], sAl + aoff[1] + kb2);
#pragma unroll
            for (int m = 0; m < 4; ++m) {
                ldm_x4(bh[m], sBh + boff[m] + kb2);
                ldm_x4(bl[m], sBl + boff[m] + kb2);
            }
#pragma unroll
            for (int mt = 0; mt < 2; ++mt)
#pragma unroll
                for (int m = 0; m < 4; ++m) {
                    mma_bf16(acc[mt][2 * m], ah[mt], bh[m][0], bh[m][1]);
                    mma_bf16(acc[mt][2 * m], ah[mt], bl[m][0], bl[m][1]);
                    mma_bf16(acc[mt][2 * m], al[mt], bh[m][0], bh[m][1]);
                    mma_bf16(acc[mt][2 * m + 1], ah[mt], bh[m][2], bh[m][3]);
                    mma_bf16(acc[mt][2 * m + 1], ah[mt], bl[m][2], bl[m][3]);
                    mma_bf16(acc[mt][2 * m + 1], al[mt], bh[m][2], bh[m][3]);
                }
        }
    }

#pragma unroll
    for (int mt = 0; mt < 2; ++mt) {
        int r0v = m0 + wr + mt * 16 + g;
        int r1v = r0v + 8;
#pragma unroll
        for (int nt = 0; nt < 8; ++nt) {
            int col = wc + nt * 8 + tg * 2;
            float b0 = __ldg(&bias[col]);
            float b1 = __ldg(&bias[col + 1]);
            if (r0v < n) {
                float2 o = make_float2(acc[mt][nt][0] + b0, acc[mt][nt][1] + b1);
                *(float2*)&out[(size_t)r0v * 128 + col] = o;
            }
            if (r1v < n) {
                float2 o = make_float2(acc[mt][nt][2] + b0, acc[mt][nt][3] + b1);
                *(float2*)&out[(size_t)r1v * 128 + col] = o;
            }
        }
    }
}

// ---------------- bias combine ----------------
__global__ void bias_combine_kernel(const float* __restrict__ bd1, const float* __restrict__ bs1,
                                    const float* __restrict__ bu1, const float* __restrict__ Wu1,
                                    const float* __restrict__ bd2, const float* __restrict__ bs2,
                                    const float* __restrict__ bu2, const float* __restrict__ Wu2) {
    int layer = blockIdx.x >> 1;
    int which = blockIdx.x & 1;
    int h = threadIdx.x;
    const float* bd = layer ? bd2 : bd1;
    const float* bs = layer ? bs2 : bs1;
    const float* bu = layer ? bu2 : bu1;
    const float* Wu = layer ? Wu2 : Wu1;
    auto cfun = [&](int i) {
        float s = bu[i * 128 + h];
        const float* wt = Wu + (size_t)i * WU;
        for (int k = 0; k < 128; ++k) s = fmaf(bd[i * 128 + k], wt[k * 128 + h], s);
        const float* wb = wt + WUB;
        for (int k = 0; k < 128; ++k) s = fmaf(bs[i * 128 + k], wb[k * 128 + h], s);
        return s;
    };
    if (which == 0)
        d_bg[layer][h] = 0.5f * (cfun(0) + cfun(2));
    else
        d_bd[layer][h] = cfun(1);
}

// ---------------- batch norm (separate stats; final folded into apply) ----------------
__global__ void bn_stats_kernel(const float* __restrict__ xg, const float* __restrict__ xd, int gb) {
    int c = threadIdx.x;
    bool gene = (int)blockIdx.x < gb;
    const float* x = gene ? xg : xd;
    int nn = gene ? NG : ND;
    int b = gene ? blockIdx.x : (blockIdx.x - gb);
    int r0 = b * 128;
    int rend = min(r0 + 128, nn);
    float s = 0.f, s2 = 0.f;
    for (int r = r0; r < rend; ++r) {
        float v = x[(size_t)r * 128 + c];
        s += v;
        s2 = fmaf(v, v, s2);
    }
    int off = gene ? 0 : 128;
    atomicAdd(&d_bn_acc[off + c], s);
    atomicAdd(&d_bn_acc[256 + off + c], s2);
}
__global__ void bn_apply_kernel(const float* __restrict__ xg, const float* __restrict__ xd,
                                const float* __restrict__ gamma, const float* __restrict__ beta) {
    int i = blockIdx.x * blockDim.x + threadIdx.x;
    int which;
    const float* x;
    __nv_bfloat16 *oh, *ol;
    if (i < NG * 32) { which = 0; x = xg; oh = d_xg_h; ol = d_xg_l; }
    else if (i < (NG + ND) * 32) { which = 1; x = xd; oh = d_xd_h; ol = d_xd_l; i -= NG * 32; }
    else return;
    int q = i & 31;
    int c = q * 4;
    int off = which * 128;
    float nn = which == 0 ? (float)NG : (float)ND;
    float sc[4], sh[4];
#pragma unroll
    for (int k = 0; k < 4; ++k) {
        float mean = __ldg(&d_bn_acc[off + c + k]) / nn;
        float var = __ldg(&d_bn_acc[256 + off + c + k]) / nn - mean * mean;
        float s = __ldg(&gamma[off + c + k]) * rsqrtf(var + 1e-5f);
        sc[k] = s;
        sh[k] = __ldg(&beta[off + c + k]) - mean * s;
    }
    float4 v = *(const float4*)&x[(size_t)i * 4];
    v.x = fmaf(v.x, sc[0], sh[0]);
    v.y = fmaf(v.y, sc[1], sh[1]);
    v.z = fmaf(v.z, sc[2], sh[2]);
    v.w = fmaf(v.w, sc[3], sh[3]);
    v.x = v.x >= 0.f ? v.x : 0.01f * v.x;
    v.y = v.y >= 0.f ? v.y : 0.01f * v.y;
    v.z = v.z >= 0.f ? v.z : 0.01f * v.z;
    v.w = v.w >= 0.f ? v.w : 0.01f * v.w;
    uint2 uh, ul;
    split2(v.x, v.y, uh.x, ul.x);
    split2(v.z, v.w, uh.y, ul.y);
    *(uint2*)&oh[(size_t)i * 4] = uh;
    *(uint2*)&ol[(size_t)i * 4] = ul;
}

// ---------------- decoder ----------------
__global__ void decode_kernel(const int* __restrict__ ls, const int* __restrict__ ld,
                              float* __restrict__ out) {
    int gw = (blockIdx.x * blockDim.x + threadIdx.x) >> 5;
    int lane = threadIdx.x & 31;
    if (gw >= ELAB) return;
    int a = __ldg(&ls[gw]);
    int b = __ldg(&ld[gw]);
    float4 u = *(const float4*)&d_g2[(size_t)a * 128 + lane * 4];
    float4 v = *(const float4*)&d_d2[(size_t)b * 128 + lane * 4];
    float s = u.x * v.x + u.y * v.y + u.z * v.z + u.w * v.w;
#pragma unroll
    for (int o = 16; o; o >>= 1) s += __shfl_xor_sync(0xFFFFFFFFu, s, o);
    if (lane == 0) out[gw] = s;
}

// ---------------- launch ----------------
static inline int cdiv(int a, int b) { return (a + b - 1) / b; }

extern "C" void kernel_launch(void* const* d_in, const int* in_sizes, int n_in,
                              void* d_out, int out_size) {
    const float* x_gene = (const float*)d_in[0];
    const float* x_dis  = (const float*)d_in[1];
    const float* W_dst1 = (const float*)d_in[2];
    const float* W_src1 = (const float*)d_in[3];
    const float* W_upd1 = (const float*)d_in[4];
    const float* b_dst1 = (const float*)d_in[5];
    const float* b_src1 = (const float*)d_in[6];
    const float* b_upd1 = (const float*)d_in[7];
    const float* W_dst2 = (const float*)d_in[8];
    const float* W_src2 = (const float*)d_in[9];
    const float* W_upd2 = (const float*)d_in[10];
    const float* b_dst2 = (const float*)d_in[11];
    const float* b_src2 = (const float*)d_in[12];
    const float* b_upd2 = (const float*)d_in[13];
    const float* bn_gamma = (const float*)d_in[14];
    const float* bn_beta  = (const float*)d_in[15];
    const int* gg_src  = (const int*)d_in[16];
    const int* gg_dst  = (const int*)d_in[17];
    const int* gda_src = (const int*)d_in[18];
    const int* gda_dst = (const int*)d_in[19];
    const int* label_src = (const int*)d_in[20];
    const int* label_dst = (const int*)d_in[21];
    float* out = (float*)d_out;

    static cudaStream_t s2 = nullptr;
    static cudaEvent_t e0 = nullptr, e1 = nullptr;
    if (!s2) {
        cudaFuncSetAttribute(mmagemm_kernel, cudaFuncAttributeMaxDynamicSharedMemorySize, SMEM_TOTAL);
        cudaStreamCreateWithFlags(&s2, cudaStreamNonBlocking);
        cudaEventCreateWithFlags(&e0, cudaEventDisableTiming);
        cudaEventCreateWithFlags(&e1, cudaEventDisableTiming);
    }

    float *g1, *d1, *g2, *d2, *bg, *bd;
    __nv_bfloat16 *Wh, *Wl;
    cudaGetSymbolAddress((void**)&g1, d_g1);
    cudaGetSymbolAddress((void**)&d1, d_d1);
    cudaGetSymbolAddress((void**)&g2, d_g2);
    cudaGetSymbolAddress((void**)&d2, d_d2);
    cudaGetSymbolAddress((void**)&Wh, d_Wh);
    cudaGetSymbolAddress((void**)&Wl, d_Wl);
    cudaGetSymbolAddress((void**)&bg, d_bg);
    cudaGetSymbolAddress((void**)&bd, d_bd);

    const int GB = cdiv(NG, 128), DB = cdiv(ND, 128);

    // fork: side stream converts inputs + preps weights while main builds CSR
    cudaEventRecord(e0, 0);
    cudaStreamWaitEvent(s2, e0, 0);
    tobf16_kernel<<<cdiv((NG + ND) * 32, 256), 256, 0, s2>>>(x_gene, x_dis);
    wprep_kernel<<<10, 256, 0, s2>>>(W_dst1, W_src1, W_upd1, W_dst2, W_src2, W_upd2, Wh, Wl);
    bias_combine_kernel<<<4, 128, 0, s2>>>(b_dst1, b_src1, b_upd1, W_upd1,
                                           b_dst2, b_src2, b_upd2, W_upd2);
    cudaEventRecord(e1, s2);

    // main: CSR build
    init_kernel<<<cdiv(NTOT + 512, 256), 256>>>();
    deg_all_kernel<<<cdiv(ETOT, 256), 256>>>(gg_dst, gda_dst, gda_src);
    scan_all_kernel<<<3, 1024>>>();
    fill_all_kernel<<<cdiv(ETOT, 256), 256>>>(gg_src, gg_dst, gda_src, gda_dst);

    // join
    cudaStreamWaitEvent(0, e1, 0);

    // layer-1 aggregation + GEMM
    gather_all_kernel<<<cdiv(NTOT * 32, 256), 256>>>();
    mmagemm_kernel<<<GBR + DBR, 256, SMEM_TOTAL>>>(Wh, Wl, bg, bd, g1, d1);

    // BN stats + apply (final folded into apply)
    bn_stats_kernel<<<GB + DB, 128>>>(g1, d1, GB);
    bn_apply_kernel<<<cdiv((NG + ND) * 32, 256), 256>>>(g1, d1, bn_gamma, bn_beta);

    // layer-2 aggregation + GEMM
    gather_all_kernel<<<cdiv(NTOT * 32, 256), 256>>>();
    mmagemm_kernel<<<GBR + DBR, 256, SMEM_TOTAL>>>(Wh + 5 * MM, Wl + 5 * MM,
                                                   bg + HD, bd + HD, g2, d2);

    // decoder
    decode_kernel<<<cdiv(ELAB * 32, 256), 256>>>(label_src, label_dst, out);
}